// round 1
// baseline (speedup 1.0000x reference)
#include <cuda_runtime.h>

// Problem constants (fixed shapes for EpisodicMemory_57810259804539)
#define BB 4
#define HH 16
#define SS 2048
#define DD 64
#define MM 1000
#define KK 10
#define HID (HH*DD)       // 1024
#define TT (SS+KK)        // 2058
#define EPSV 1e-8

// Scratch (no allocations allowed in kernel_launch)
__device__ double g_qn[BB*HID];     // normalized query key per batch (double)
__device__ double g_sims[BB*MM];    // cosine sims
__device__ int    g_top[BB*KK];     // top-k indices per batch

// ---------------------------------------------------------------------------
// A0: build query_key[b] = k[b, :, S-1, :] flattened, normalize by (||.||+eps)
// ---------------------------------------------------------------------------
__global__ void qn_kernel(const float* __restrict__ k)
{
    int b = blockIdx.x;
    __shared__ double red[256];
    __shared__ float  qk[HID];

    double s = 0.0;
    for (int i = threadIdx.x; i < HID; i += 256) {
        int h = i / DD, d = i % DD;
        float vv = k[(((size_t)b*HH + h)*SS + (SS-1))*DD + d];
        qk[i] = vv;
        s += (double)vv * (double)vv;
    }
    red[threadIdx.x] = s;
    __syncthreads();
    for (int off = 128; off; off >>= 1) {
        if (threadIdx.x < off) red[threadIdx.x] += red[threadIdx.x + off];
        __syncthreads();
    }
    double inv = 1.0 / (sqrt(red[0]) + EPSV);
    for (int i = threadIdx.x; i < HID; i += 256)
        g_qn[b*HID + i] = (double)qk[i] * inv;
}

// ---------------------------------------------------------------------------
// A1: one warp per (b, m): sim = dot(qn, mem_row) / (||mem_row|| + eps)
// ---------------------------------------------------------------------------
__global__ void sims_kernel(const float* __restrict__ mk)
{
    int warp = (int)((blockIdx.x * (long long)blockDim.x + threadIdx.x) >> 5);
    int lane = threadIdx.x & 31;
    if (warp >= BB*MM) return;
    int b = warp / MM, m = warp % MM;

    const float*  row = mk + (size_t)m * HID;
    const double* qn  = g_qn + (size_t)b * HID;

    double dot = 0.0, sq = 0.0;
    #pragma unroll 4
    for (int i = lane; i < HID; i += 32) {
        double vv = (double)row[i];
        dot += qn[i] * vv;
        sq  += vv * vv;
    }
    #pragma unroll
    for (int off = 16; off; off >>= 1) {
        dot += __shfl_down_sync(0xffffffffu, dot, off);
        sq  += __shfl_down_sync(0xffffffffu, sq,  off);
    }
    if (lane == 0)
        g_sims[warp] = dot / (sqrt(sq) + EPSV);
}

// ---------------------------------------------------------------------------
// A2: per-batch top-10 (jax.lax.top_k: descending, lowest index on ties),
//     then write mask_aug, positions_k, and the seq_len_k scalar.
// ---------------------------------------------------------------------------
__global__ void topk_kernel(const float* __restrict__ attn_mask,
                            const float* __restrict__ mem_pos,
                            float* __restrict__ out,
                            long long off_mask, long long off_pos,
                            long long off_seq, int has_scalar)
{
    int b = blockIdx.x;
    __shared__ double ss[MM];
    __shared__ int    top[KK];

    for (int i = threadIdx.x; i < MM; i += blockDim.x)
        ss[i] = g_sims[b*MM + i];
    __syncthreads();

    if (threadIdx.x == 0) {
        for (int j = 0; j < KK; j++) {
            double best = -1e300; int bi = 0;
            for (int m = 0; m < MM; m++) {
                if (ss[m] > best) { best = ss[m]; bi = m; }  // strict > => lowest idx on tie
            }
            top[j] = bi;
            ss[bi] = -1e301;
            g_top[b*KK + j] = bi;
        }
    }
    __syncthreads();

    // mask_aug[b] = [ones(K), attention_mask[b]]
    for (int t = threadIdx.x; t < TT; t += blockDim.x)
        out[off_mask + (size_t)b*TT + t] =
            (t < KK) ? 1.0f : attn_mask[(size_t)b*SS + (t - KK)];

    // positions_k[b] = [arange(S), mem_positions[top_idx[b]]]
    for (int t = threadIdx.x; t < TT; t += blockDim.x)
        out[off_pos + (size_t)b*TT + t] =
            (t < SS) ? (float)t : mem_pos[top[t - SS]];

    if (b == 0 && threadIdx.x == 0 && has_scalar)
        out[off_seq] = (float)TT;
}

// ---------------------------------------------------------------------------
// B: assemble k_aug and v_aug, float4-vectorized.
//    out[b,h,t,d]: t<K -> mem_{k,v}[top[b,t], h*D+d];  else k/v[b,h,t-K,d]
// ---------------------------------------------------------------------------
__global__ void assemble_kernel(const float* __restrict__ k,
                                const float* __restrict__ v,
                                const float* __restrict__ mk,
                                const float* __restrict__ mv,
                                float4* __restrict__ outk,
                                float4* __restrict__ outv)
{
    const int D4 = DD / 4;                                   // 16
    const long long per = (long long)BB * HH * TT * D4;      // 2,107,392
    long long e = (long long)blockIdx.x * blockDim.x + threadIdx.x;
    int which = 0;
    if (e >= per) { which = 1; e -= per; }
    if (e >= per) return;

    int d4 = (int)(e % D4);
    int t  = (int)((e / D4) % TT);
    int h  = (int)((e / ((long long)D4 * TT)) % HH);
    int b  = (int)(e / ((long long)D4 * TT * HH));

    float4 val;
    if (t < KK) {
        int idx = g_top[b*KK + t];
        const float* base = which ? mv : mk;
        val = ((const float4*)(base + (size_t)idx*HID + (size_t)h*DD))[d4];
    } else {
        const float* base = which ? v : k;
        val = ((const float4*)(base + (((size_t)b*HH + h)*SS + (t - KK))*(size_t)DD))[d4];
    }
    float4* dst = which ? outv : outk;
    dst[(((size_t)b*HH + h)*TT + t)*D4 + d4] = val;
}

// ---------------------------------------------------------------------------
extern "C" void kernel_launch(void* const* d_in, const int* in_sizes, int n_in,
                              void* d_out, int out_size)
{
    const float* inputs = (const float*)d_in[0];
    const float* q      = (const float*)d_in[1];
    const float* k      = (const float*)d_in[2];
    const float* v      = (const float*)d_in[3];
    const float* mask   = (const float*)d_in[4];
    const float* mk     = (const float*)d_in[5];
    const float* mv     = (const float*)d_in[6];
    const float* mpos   = (const float*)d_in[7];
    float* out = (float*)d_out;

    const long long N0 = (long long)BB * SS * HID;   // 8,388,608  (inputs)
    const long long NQ = (long long)BB * HH * SS * DD; // 8,388,608 (q)
    const long long NK = (long long)BB * HH * TT * DD; // 8,429,568 (k_aug / v_aug)

    const long long off_q    = N0;
    const long long off_k    = off_q + NQ;
    const long long off_v    = off_k + NK;
    const long long off_mask = off_v + NK;
    const long long off_tail = off_mask + (long long)BB * TT;
    // tuple order: inputs, q, k_aug, v_aug, mask_aug, seq_len_k, positions_k
    const long long with_scalar = off_tail + 1 + (long long)BB * TT;
    int has_scalar = ((long long)out_size == with_scalar) ? 1 : 0;
    const long long off_seq = off_tail;
    const long long off_pos = off_tail + (has_scalar ? 1 : 0);

    // Pass-through copies (graph-capturable DtoD memcpys)
    cudaMemcpyAsync(out,          inputs, (size_t)N0 * sizeof(float),
                    cudaMemcpyDeviceToDevice, 0);
    cudaMemcpyAsync(out + off_q,  q,      (size_t)NQ * sizeof(float),
                    cudaMemcpyDeviceToDevice, 0);

    // Retrieval path
    qn_kernel<<<BB, 256>>>(k);
    {
        int warps = BB * MM;                    // 4000
        int threads = 256;
        int blocks = (warps * 32 + threads - 1) / threads; // 500
        sims_kernel<<<blocks, threads>>>(mk);
    }
    topk_kernel<<<BB, 256>>>(mask, mpos, out, off_mask, off_pos, off_seq, has_scalar);

    // k_aug / v_aug assembly (float4)
    {
        long long per = (long long)BB * HH * TT * (DD / 4);
        long long tot = 2 * per;
        int threads = 256;
        int blocks = (int)((tot + threads - 1) / threads);
        assemble_kernel<<<blocks, threads>>>(k, v, mk, mv,
                                             (float4*)(out + off_k),
                                             (float4*)(out + off_v));
    }
}

// round 2
// speedup vs baseline: 5.9003x; 5.9003x over previous
#include <cuda_runtime.h>
#include <math.h>

// Problem constants (fixed shapes for EpisodicMemory_57810259804539)
#define BB 4
#define HH 16
#define SS 2048
#define DD 64
#define MM 1000
#define KK 10
#define HID (HH*DD)       // 1024
#define TT (SS+KK)        // 2058
#define EPSV 1e-8

#define N0_4  ((long long)BB*SS*HID/4)       // 2,097,152  inputs as float4
#define NQ_4  ((long long)BB*HH*SS*DD/4)     // 2,097,152  q as float4
#define NK_4  ((long long)BB*HH*TT*DD/4)     // 2,107,392  k_aug/v_aug as float4

// Scratch (no allocations allowed in kernel_launch)
__device__ double g_qn[BB*HID];     // normalized query key per batch (double)
__device__ double g_sims[BB*MM];    // cosine sims
__device__ int    g_top[BB*KK];     // top-k indices per batch

// ---------------------------------------------------------------------------
// A0: query_key[b] = k[b, :, S-1, :] flattened, normalized by (||.||+eps)
// ---------------------------------------------------------------------------
__global__ void qn_kernel(const float* __restrict__ k)
{
    int b = blockIdx.x;
    __shared__ double red[256];
    __shared__ float  qk[HID];

    double s = 0.0;
    for (int i = threadIdx.x; i < HID; i += 256) {
        int h = i / DD, d = i % DD;
        float vv = k[(((size_t)b*HH + h)*SS + (SS-1))*DD + d];
        qk[i] = vv;
        s += (double)vv * (double)vv;
    }
    red[threadIdx.x] = s;
    __syncthreads();
    for (int off = 128; off; off >>= 1) {
        if (threadIdx.x < off) red[threadIdx.x] += red[threadIdx.x + off];
        __syncthreads();
    }
    double inv = 1.0 / (sqrt(red[0]) + EPSV);
    for (int i = threadIdx.x; i < HID; i += 256)
        g_qn[b*HID + i] = (double)qk[i] * inv;
}

// ---------------------------------------------------------------------------
// A1: one warp per (b, m): sim = dot(qn, mem_row) / (||mem_row|| + eps)
// ---------------------------------------------------------------------------
__global__ void sims_kernel(const float* __restrict__ mk)
{
    int warp = (int)((blockIdx.x * (long long)blockDim.x + threadIdx.x) >> 5);
    int lane = threadIdx.x & 31;
    if (warp >= BB*MM) return;
    int b = warp / MM, m = warp % MM;

    const float*  row = mk + (size_t)m * HID;
    const double* qn  = g_qn + (size_t)b * HID;

    double dot = 0.0, sq = 0.0;
    #pragma unroll 4
    for (int i = lane; i < HID; i += 32) {
        double vv = (double)row[i];
        dot += qn[i] * vv;
        sq  += vv * vv;
    }
    #pragma unroll
    for (int off = 16; off; off >>= 1) {
        dot += __shfl_down_sync(0xffffffffu, dot, off);
        sq  += __shfl_down_sync(0xffffffffu, sq,  off);
    }
    if (lane == 0)
        g_sims[warp] = dot / (sqrt(sq) + EPSV);
}

// ---------------------------------------------------------------------------
// A2: per-batch PARALLEL top-10 (descending, lowest index on ties),
//     then write mask_aug, positions_k, seq_len_k scalar.
// ---------------------------------------------------------------------------
__global__ void topk_kernel(const float* __restrict__ attn_mask,
                            const float* __restrict__ mem_pos,
                            float* __restrict__ out,
                            long long off_mask, long long off_pos,
                            long long off_seq, int has_scalar)
{
    int b = blockIdx.x;
    int tid = threadIdx.x;
    __shared__ double ss[MM];
    __shared__ double rv[256];
    __shared__ int    ri[256];
    __shared__ int    top[KK];

    for (int i = tid; i < MM; i += 256)
        ss[i] = g_sims[b*MM + i];
    __syncthreads();

    for (int j = 0; j < KK; j++) {
        // thread-local scan (indices increase, so strict > keeps lowest idx)
        double bv = -INFINITY; int bi = MM;
        for (int m = tid; m < MM; m += 256) {
            double vv = ss[m];
            if (vv > bv) { bv = vv; bi = m; }
        }
        rv[tid] = bv; ri[tid] = bi;
        __syncthreads();
        // tree reduce: larger value wins; equal value -> smaller index
        for (int off = 128; off; off >>= 1) {
            if (tid < off) {
                double ov = rv[tid + off]; int oi = ri[tid + off];
                if (ov > rv[tid] || (ov == rv[tid] && oi < ri[tid])) {
                    rv[tid] = ov; ri[tid] = oi;
                }
            }
            __syncthreads();
        }
        if (tid == 0) {
            int sel = ri[0];
            top[j] = sel;
            g_top[b*KK + j] = sel;
            ss[sel] = -INFINITY;
        }
        __syncthreads();
    }

    // mask_aug[b] = [ones(K), attention_mask[b]]
    for (int t = tid; t < TT; t += 256)
        out[off_mask + (size_t)b*TT + t] =
            (t < KK) ? 1.0f : attn_mask[(size_t)b*SS + (t - KK)];

    // positions_k[b] = [arange(S), mem_positions[top_idx[b]]]
    for (int t = tid; t < TT; t += 256)
        out[off_pos + (size_t)b*TT + t] =
            (t < SS) ? (float)t : mem_pos[top[t - SS]];

    if (b == 0 && tid == 0 && has_scalar)
        out[off_seq] = (float)TT;
}

// ---------------------------------------------------------------------------
// B: MEGA kernel — inputs copy, q copy, k_aug, v_aug, all float4.
//    One launch, SM-side copies at LTS bandwidth.
// ---------------------------------------------------------------------------
__global__ void __launch_bounds__(256) mega_kernel(
    const float4* __restrict__ inputs4,
    const float4* __restrict__ q4,
    const float*  __restrict__ k,
    const float*  __restrict__ v,
    const float*  __restrict__ mk,
    const float*  __restrict__ mv,
    float4* __restrict__ out4)       // out as float4 (offsets all /4)
{
    const int D4 = DD / 4;                                   // 16
    long long e = (long long)blockIdx.x * 256 + threadIdx.x;

    // Region 0: inputs pass-through
    if (e < N0_4) { out4[e] = inputs4[e]; return; }
    e -= N0_4;
    // Region 1: q pass-through
    if (e < NQ_4) { out4[N0_4 + NQ_4 - NQ_4 + N0_4 - N0_4 + N0_4 + e - N0_4 + NQ_4 - NQ_4 + N0_4 - N0_4] = q4[e]; }
    if (e < NQ_4) { out4[N0_4 + e] = q4[e]; return; }
    e -= NQ_4;
    // Regions 2/3: k_aug / v_aug
    int which = 0;
    if (e >= NK_4) { which = 1; e -= NK_4; }
    if (e >= NK_4) return;

    int d4 = (int)(e & (D4 - 1));
    long long r = e >> 4;              // (b*H + h)*TT + t
    int t  = (int)(r % TT);
    int bh = (int)(r / TT);
    int h  = bh & (HH - 1);
    int b  = bh >> 4;

    float4 val;
    if (t < KK) {
        int idx = g_top[b*KK + t];
        const float* base = which ? mv : mk;
        val = ((const float4*)(base + (size_t)idx*HID + (size_t)h*DD))[d4];
    } else {
        const float* base = which ? v : k;
        val = ((const float4*)(base + ((size_t)bh*SS + (t - KK))*(size_t)DD))[d4];
    }
    long long dst = N0_4 + NQ_4 + (long long)which*NK_4 + e;
    out4[dst] = val;
}

// ---------------------------------------------------------------------------
extern "C" void kernel_launch(void* const* d_in, const int* in_sizes, int n_in,
                              void* d_out, int out_size)
{
    const float* inputs = (const float*)d_in[0];
    const float* q      = (const float*)d_in[1];
    const float* k      = (const float*)d_in[2];
    const float* v      = (const float*)d_in[3];
    const float* mask   = (const float*)d_in[4];
    const float* mk     = (const float*)d_in[5];
    const float* mv     = (const float*)d_in[6];
    const float* mpos   = (const float*)d_in[7];
    float* out = (float*)d_out;

    const long long N0 = 4 * N0_4;
    const long long NQ = 4 * NQ_4;
    const long long NK = 4 * NK_4;

    const long long off_mask = N0 + NQ + 2*NK;
    const long long off_tail = off_mask + (long long)BB * TT;
    // tuple order: inputs, q, k_aug, v_aug, mask_aug, seq_len_k, positions_k
    const long long with_scalar = off_tail + 1 + (long long)BB * TT;
    int has_scalar = ((long long)out_size == with_scalar) ? 1 : 0;
    const long long off_seq = off_tail;
    const long long off_pos = off_tail + (has_scalar ? 1 : 0);

    // Retrieval path
    qn_kernel<<<BB, 256>>>(k);
    {
        int warps = BB * MM;                    // 4000
        int threads = 256;
        int blocks = (warps * 32 + threads - 1) / threads; // 500
        sims_kernel<<<blocks, threads>>>(mk);
    }
    topk_kernel<<<BB, 256>>>(mask, mpos, out, off_mask, off_pos, off_seq, has_scalar);

    // All bulk data movement in one kernel
    {
        long long tot = N0_4 + NQ_4 + 2*NK_4;   // 8,409,088 float4
        int threads = 256;
        int blocks = (int)((tot + threads - 1) / threads);
        mega_kernel<<<blocks, threads>>>((const float4*)inputs, (const float4*)q,
                                         k, v, mk, mv, (float4*)out);
    }
}

// round 3
// speedup vs baseline: 12.5499x; 2.1270x over previous
#include <cuda_runtime.h>
#include <math.h>

// Fixed shapes for EpisodicMemory_57810259804539
#define BB 4
#define HH 16
#define SS 2048
#define DD 64
#define MM 1000
#define KK 10
#define HID (HH*DD)       // 1024
#define TT (SS+KK)        // 2058
#define EPSV 1e-8f

#define N0_4  ((long long)BB*SS*HID/4)         // 2,097,152  inputs as float4
#define NQ_4  N0_4                              // 2,097,152  q as float4
#define NB_4  ((long long)BB*HH*SS*DD/4)        // 2,097,152  k/v body as float4
#define NK_4  ((long long)BB*HH*TT*DD/4)        // 2,107,392  k_aug/v_aug as float4
#define HID4  (HID/4)                           // 256 float4 per memory row

// Scratch
__device__ float g_sims[BB*MM];

// ---------------------------------------------------------------------------
// K1: one warp per (b,m):
//   sim = dot(query_key[b], mem_row[m]) / (||mem_row[m]|| + eps)
// (query-key normalization dropped: positive per-batch scale, ordering-invariant)
// ---------------------------------------------------------------------------
__global__ void __launch_bounds__(256) sims_kernel(const float* __restrict__ k,
                                                   const float* __restrict__ mk)
{
    int warp = (blockIdx.x * 256 + threadIdx.x) >> 5;
    int lane = threadIdx.x & 31;
    if (warp >= BB*MM) return;
    int b = warp / MM, m = warp % MM;

    const float4* row = (const float4*)(mk + (size_t)m * HID);
    // query_key[b][i] = k[b, i/64, S-1, i%64]; float4 chunks never cross h.
    const float*  kb  = k + (((size_t)b*HH)*SS + (SS-1))*DD;   // + h*SS*DD + d

    float dot = 0.f, sq = 0.f;
    #pragma unroll
    for (int j = 0; j < 8; j++) {
        int i4 = lane + 32*j;                 // 0..255
        float4 r = row[i4];
        int h  = i4 >> 4;                     // (4*i4)/64
        int d4 = i4 & 15;
        float4 qv = ((const float4*)(kb + (size_t)h*SS*DD))[d4];
        dot += qv.x*r.x + qv.y*r.y + qv.z*r.z + qv.w*r.w;
        sq  += r.x*r.x + r.y*r.y + r.z*r.z + r.w*r.w;
    }
    #pragma unroll
    for (int off = 16; off; off >>= 1) {
        dot += __shfl_down_sync(0xffffffffu, dot, off);
        sq  += __shfl_down_sync(0xffffffffu, sq,  off);
    }
    if (lane == 0)
        g_sims[warp] = dot / (sqrtf(sq) + EPSV);
}

// ---------------------------------------------------------------------------
// K2: mega kernel.
//   blocks 0..3   : per-batch top-10 + gather rows t<K + mask_aug + positions_k
//   blocks 4..    : bulk float4 copies (inputs, q, k body, v body)
// Copy blocks don't depend on top-k, so retrieval hides under the copy.
// ---------------------------------------------------------------------------
__global__ void __launch_bounds__(256) mega2_kernel(
    const float4* __restrict__ inputs4,
    const float4* __restrict__ q4,
    const float4* __restrict__ k4,
    const float4* __restrict__ v4,
    const float4* __restrict__ mk4,
    const float4* __restrict__ mv4,
    const float*  __restrict__ attn_mask,
    const float*  __restrict__ mem_pos,
    float4* __restrict__ out4,
    float*  __restrict__ out,
    long long off_mask, long long off_pos,
    long long off_seq, int has_scalar)
{
    const long long OFFK4 = N0_4 + NQ_4;            // k_aug start (float4)
    const long long OFFV4 = OFFK4 + NK_4;           // v_aug start

    if (blockIdx.x < BB) {
        // ---------------- retrieval block for batch b ----------------
        int b = blockIdx.x;
        int tid = threadIdx.x;
        __shared__ float ss[MM];
        __shared__ float rv[256];
        __shared__ int   ri[256];
        __shared__ int   top[KK];

        for (int i = tid; i < MM; i += 256)
            ss[i] = g_sims[b*MM + i];
        __syncthreads();

        for (int j = 0; j < KK; j++) {
            float bv = -INFINITY; int bi = MM;
            for (int m = tid; m < MM; m += 256) {
                float vv = ss[m];
                if (vv > bv) { bv = vv; bi = m; }   // strict > => lowest idx wins
            }
            rv[tid] = bv; ri[tid] = bi;
            __syncthreads();
            for (int off = 128; off; off >>= 1) {
                if (tid < off) {
                    float ov = rv[tid + off]; int oi = ri[tid + off];
                    if (ov > rv[tid] || (ov == rv[tid] && oi < ri[tid])) {
                        rv[tid] = ov; ri[tid] = oi;
                    }
                }
                __syncthreads();
            }
            if (tid == 0) { top[j] = ri[0]; ss[ri[0]] = -INFINITY; }
            __syncthreads();
        }

        // gather rows t<K of k_aug / v_aug: 2 * K * 256 float4 = 5120
        for (int e = tid; e < 2*KK*HID4; e += 256) {
            int which = e >= KK*HID4;
            int e2 = which ? e - KK*HID4 : e;
            int t  = e2 >> 8;          // 0..9
            int i4 = e2 & 255;         // h*16 + d4
            int idx = top[t];
            float4 val = (which ? mv4 : mk4)[(size_t)idx*HID4 + i4];
            long long dst = (which ? OFFV4 : OFFK4)
                          + (((long long)b*HH + (i4 >> 4))*TT + t)*16 + (i4 & 15);
            out4[dst] = val;
        }

        // mask_aug[b] = [ones(K), attention_mask[b]]
        for (int t = tid; t < TT; t += 256)
            out[off_mask + (size_t)b*TT + t] =
                (t < KK) ? 1.0f : attn_mask[(size_t)b*SS + (t - KK)];

        // positions_k[b] = [arange(S), mem_positions[top_idx[b]]]
        for (int t = tid; t < TT; t += 256)
            out[off_pos + (size_t)b*TT + t] =
                (t < SS) ? (float)t : mem_pos[top[t - SS]];

        if (b == 0 && tid == 0 && has_scalar)
            out[off_seq] = (float)TT;
        return;
    }

    // ---------------- bulk copy blocks ----------------
    long long e = (long long)(blockIdx.x - BB) * 256 + threadIdx.x;

    if (e < N0_4) { out4[e] = inputs4[e]; return; }
    e -= N0_4;
    if (e < NQ_4) { out4[N0_4 + e] = q4[e]; return; }
    e -= NQ_4;
    // k body: src contiguous; dst skips K retrieved rows per (b,h)
    if (e < NB_4) {
        int d4 = (int)(e & 15);
        long long r = e >> 4;
        int t  = (int)(r & (SS - 1));
        int bh = (int)(r >> 11);
        out4[OFFK4 + (((long long)bh)*TT + KK + t)*16 + d4] = k4[e];
        return;
    }
    e -= NB_4;
    if (e < NB_4) {
        int d4 = (int)(e & 15);
        long long r = e >> 4;
        int t  = (int)(r & (SS - 1));
        int bh = (int)(r >> 11);
        out4[OFFV4 + (((long long)bh)*TT + KK + t)*16 + d4] = v4[e];
    }
}

// ---------------------------------------------------------------------------
extern "C" void kernel_launch(void* const* d_in, const int* in_sizes, int n_in,
                              void* d_out, int out_size)
{
    const float* inputs = (const float*)d_in[0];
    const float* q      = (const float*)d_in[1];
    const float* k      = (const float*)d_in[2];
    const float* v      = (const float*)d_in[3];
    const float* mask   = (const float*)d_in[4];
    const float* mk     = (const float*)d_in[5];
    const float* mv     = (const float*)d_in[6];
    const float* mpos   = (const float*)d_in[7];
    float* out = (float*)d_out;

    const long long N0 = 4 * N0_4;
    const long long NQ = 4 * NQ_4;
    const long long NK = 4 * NK_4;

    const long long off_mask = N0 + NQ + 2*NK;
    const long long off_tail = off_mask + (long long)BB * TT;
    // tuple order: inputs, q, k_aug, v_aug, mask_aug, seq_len_k, positions_k
    const long long with_scalar = off_tail + 1 + (long long)BB * TT;
    int has_scalar = ((long long)out_size == with_scalar) ? 1 : 0;
    const long long off_seq = off_tail;
    const long long off_pos = off_tail + (has_scalar ? 1 : 0);

    // K1: similarities (4000 warps, fp32)
    {
        int warps = BB * MM;                         // 4000
        int blocks = (warps * 32 + 255) / 256;       // 500
        sims_kernel<<<blocks, 256>>>(k, mk);
    }

    // K2: retrieval blocks + bulk copy in one launch
    {
        long long copy4 = N0_4 + NQ_4 + 2*NB_4;      // 8,388,608 float4
        int copy_blocks = (int)((copy4 + 255) / 256); // 32768
        mega2_kernel<<<BB + copy_blocks, 256>>>(
            (const float4*)inputs, (const float4*)q,
            (const float4*)k, (const float4*)v,
            (const float4*)mk, (const float4*)mv,
            mask, mpos,
            (float4*)out, out,
            off_mask, off_pos, off_seq, has_scalar);
    }
}